// round 2
// baseline (speedup 1.0000x reference)
#include <cuda_runtime.h>
#include <math.h>
#include <stdint.h>

// Problem constants
#define B_    4
#define E_    8
#define C_    128
#define NOUT  512          // both branches' conv outputs: ctx 0..255, main 256..511
#define KW    512          // conv kernel width == stride
#define T_    1000000
#define TOUT  1953         // (T - KW)/KW + 1
#define KDIM  4096         // E_*KW, contiguous window length in x

// GEMM tiling
#define BM 128
#define BN 128
#define BK 16

#define TT1 16             // t-chunk for glu+share epilogue
#define TT3 128            // t-chunk for gate+max epilogue

// -------- device scratch (no allocations allowed) --------
__device__ float d_Wr[NOUT * KDIM];                 // reordered weights, 8 MB
__device__ float d_y[(size_t)B_ * NOUT * TOUT];     // conv outputs, ~16 MB
__device__ float d_hmain[(size_t)B_ * C_ * TOUT];   // main branch activations, ~4 MB
__device__ float d_gct[B_ * C_];
__device__ float d_q[B_ * C_];

__device__ __forceinline__ float sigm(float v) { return 1.0f / (1.0f + expf(-v)); }
__device__ __forceinline__ float leaky(float v) { return v >= 0.0f ? v : 0.01f * v; }

__device__ __forceinline__ void atomicMaxF(float* addr, float val) {
    int* ia = (int*)addr;
    int old = __float_as_int(*addr);
    while (__int_as_float(old) < val) {
        int assumed = old;
        old = atomicCAS(ia, assumed, __float_as_int(val));
        if (old == assumed) break;
    }
}

// -------- 1) weight re-layout: Wr[o][kk*8+e] = w[o][e][kk] --------
__global__ void reorder_w(const float* __restrict__ cw, const float* __restrict__ mw) {
    int idx = blockIdx.x * blockDim.x + threadIdx.x;   // < NOUT*KDIM
    int o = idx >> 12;
    int k = idx & 4095;
    int e = k & 7;
    int kk = k >> 3;
    float v = (o < 256) ? cw[o * KDIM + e * KW + kk]
                        : mw[(o - 256) * KDIM + e * KW + kk];
    d_Wr[idx] = v;
}

// -------- 2) init reductions --------
__global__ void init_red(float* __restrict__ out) {
    int i = blockIdx.x * blockDim.x + threadIdx.x;
    if (i < B_ * C_) {
        d_gct[i] = -INFINITY;
        out[i]   = -INFINITY;
    }
}

// -------- 3) fused dual-branch conv as GEMM --------
// y[t, o] = sum_k x[b, t*4096 + k] * Wr[o, k]  (+ conv bias)
__global__ __launch_bounds__(256, 2)
void gemm_conv(const float* __restrict__ x,
               const float* __restrict__ ctx_b,
               const float* __restrict__ main_b) {
    const int bM = blockIdx.x;          // t tile
    const int bN = blockIdx.y;          // out-channel tile (0..3)
    const int b  = blockIdx.z;
    const int t0 = bM * BM;
    const int n0 = bN * BN;

    __shared__ float As[BK][BM + 4];
    __shared__ float Bs[BK][BN + 4];

    const int tid = threadIdx.x;
    const int tm = tid & 15;            // row group (t)
    const int tn = tid >> 4;            // col group (o)

    float acc[8][8];
#pragma unroll
    for (int i = 0; i < 8; i++)
#pragma unroll
        for (int j = 0; j < 8; j++) acc[i][j] = 0.0f;

    const float* xb = x + (size_t)b * T_ * E_;

    for (int k0 = 0; k0 < KDIM; k0 += BK) {
        // load A tile (windows of x): 128 rows x 16 k, as float4
#pragma unroll
        for (int i = 0; i < 2; i++) {
            int idx4 = tid * 2 + i;             // 0..511
            int m  = idx4 >> 2;                 // row 0..127
            int kq = (idx4 & 3) * 4;            // k offset 0,4,8,12
            float4 v = make_float4(0.f, 0.f, 0.f, 0.f);
            int t = t0 + m;
            if (t < TOUT)
                v = *reinterpret_cast<const float4*>(xb + (size_t)t * KDIM + k0 + kq);
            As[kq + 0][m] = v.x; As[kq + 1][m] = v.y;
            As[kq + 2][m] = v.z; As[kq + 3][m] = v.w;
        }
        // load B tile (reordered weights)
#pragma unroll
        for (int i = 0; i < 2; i++) {
            int idx4 = tid * 2 + i;
            int n  = idx4 >> 2;
            int kq = (idx4 & 3) * 4;
            float4 v = *reinterpret_cast<const float4*>(
                &d_Wr[(size_t)(n0 + n) * KDIM + k0 + kq]);
            Bs[kq + 0][n] = v.x; Bs[kq + 1][n] = v.y;
            Bs[kq + 2][n] = v.z; Bs[kq + 3][n] = v.w;
        }
        __syncthreads();

#pragma unroll
        for (int kk = 0; kk < BK; kk++) {
            float4 a0 = *(const float4*)&As[kk][tm * 8];
            float4 a1 = *(const float4*)&As[kk][tm * 8 + 4];
            float4 b0 = *(const float4*)&Bs[kk][tn * 8];
            float4 b1 = *(const float4*)&Bs[kk][tn * 8 + 4];
            float ar[8] = {a0.x, a0.y, a0.z, a0.w, a1.x, a1.y, a1.z, a1.w};
            float br[8] = {b0.x, b0.y, b0.z, b0.w, b1.x, b1.y, b1.z, b1.w};
#pragma unroll
            for (int i = 0; i < 8; i++)
#pragma unroll
                for (int j = 0; j < 8; j++)
                    acc[i][j] = fmaf(ar[i], br[j], acc[i][j]);
        }
        __syncthreads();
    }

    // epilogue: add conv bias, write y[b][o][t]
#pragma unroll
    for (int i = 0; i < 8; i++) {
        int t = t0 + tm * 8 + i;
        if (t >= TOUT) continue;
#pragma unroll
        for (int j = 0; j < 8; j++) {
            int o = n0 + tn * 8 + j;
            float bias = (o < 256) ? ctx_b[o] : main_b[o - 256];
            d_y[((size_t)b * NOUT + o) * TOUT + t] = acc[i][j] + bias;
        }
    }
}

// -------- 4) GLU + 1x1 share conv + leaky; ctx->gct max, main->h --------
__global__ __launch_bounds__(256)
void epi_glu_share(const float* __restrict__ ws_ctx, const float* __restrict__ bs_ctx,
                   const float* __restrict__ ws_main, const float* __restrict__ bs_main) {
    const int b  = blockIdx.y;
    const int t0 = blockIdx.x * TT1;
    const int nt = min(TT1, TOUT - t0);
    const int tid = threadIdx.x;    // 256

    __shared__ float ytile[NOUT][TT1];   // 32 KB

    // load y tile
    for (int idx = tid; idx < NOUT * TT1; idx += 256) {
        int o = idx / TT1, tt = idx % TT1;
        ytile[o][tt] = (tt < nt) ? d_y[((size_t)b * NOUT + o) * TOUT + t0 + tt] : 0.0f;
    }
    __syncthreads();

    // GLU in place: rows 0..127 (ctx a*sig(g)), rows 256..383 (main)
    for (int idx = tid; idx < C_ * TT1; idx += 256) {
        int c = idx / TT1, tt = idx % TT1;
        float a1 = ytile[c][tt],          g1 = ytile[C_ + c][tt];
        float a2 = ytile[2 * C_ + c][tt], g2 = ytile[3 * C_ + c][tt];
        ytile[c][tt]          = a1 * sigm(g1);
        ytile[2 * C_ + c][tt] = a2 * sigm(g2);
    }
    __syncthreads();

    // share matvec: thread = (branch, cp); accumulate over all tt in registers
    const int branch = tid >> 7;        // 0 = ctx, 1 = main
    const int cp = tid & 127;
    const float* ws = branch ? ws_main : ws_ctx;
    const float* bs = branch ? bs_main : bs_ctx;
    const int rowbase = branch ? (2 * C_) : 0;

    float acc[TT1];
#pragma unroll
    for (int tt = 0; tt < TT1; tt++) acc[tt] = 0.0f;

    for (int c = 0; c < C_; c++) {
        float w = ws[cp * C_ + c];
        const float4* row = (const float4*)&ytile[rowbase + c][0];
        float4 v0 = row[0], v1 = row[1], v2 = row[2], v3 = row[3];
        acc[0]  = fmaf(w, v0.x, acc[0]);  acc[1]  = fmaf(w, v0.y, acc[1]);
        acc[2]  = fmaf(w, v0.z, acc[2]);  acc[3]  = fmaf(w, v0.w, acc[3]);
        acc[4]  = fmaf(w, v1.x, acc[4]);  acc[5]  = fmaf(w, v1.y, acc[5]);
        acc[6]  = fmaf(w, v1.z, acc[6]);  acc[7]  = fmaf(w, v1.w, acc[7]);
        acc[8]  = fmaf(w, v2.x, acc[8]);  acc[9]  = fmaf(w, v2.y, acc[9]);
        acc[10] = fmaf(w, v2.z, acc[10]); acc[11] = fmaf(w, v2.w, acc[11]);
        acc[12] = fmaf(w, v3.x, acc[12]); acc[13] = fmaf(w, v3.y, acc[13]);
        acc[14] = fmaf(w, v3.z, acc[14]); acc[15] = fmaf(w, v3.w, acc[15]);
    }
    float bias = bs[cp];
    if (branch == 0) {
        float m = -INFINITY;
        for (int tt = 0; tt < nt; tt++)
            m = fmaxf(m, leaky(acc[tt] + bias));
        atomicMaxF(&d_gct[b * C_ + cp], m);
    } else {
        for (int tt = 0; tt < nt; tt++)
            d_hmain[((size_t)b * C_ + cp) * TOUT + t0 + tt] = leaky(acc[tt] + bias);
    }
}

// -------- 5) q = tanh(gct @ Wp^T + bp) --------
__global__ void q_kernel(const float* __restrict__ wp, const float* __restrict__ bp) {
    int b = blockIdx.x;
    int c = threadIdx.x;
    __shared__ float g[C_];
    g[c] = d_gct[b * C_ + c];
    __syncthreads();
    float s = bp[c];
    for (int cp = 0; cp < C_; cp++)
        s = fmaf(g[cp], wp[c * C_ + cp], s);
    d_q[b * C_ + c] = tanhf(s);
}

// -------- 6) gate = sigmoid(h . q); out = max_t h*gate --------
__global__ void epi_gate_max(float* __restrict__ out) {
    const int b  = blockIdx.y;
    const int t0 = blockIdx.x * TT3;
    const int nt = min(TT3, TOUT - t0);
    const int tid = threadIdx.x;      // 128

    __shared__ float qs[C_];
    __shared__ float gate[TT3];
    qs[tid] = d_q[b * C_ + tid];
    __syncthreads();

    if (tid < nt) {
        int t = t0 + tid;
        float s = 0.0f;
        for (int c = 0; c < C_; c++)
            s = fmaf(d_hmain[((size_t)b * C_ + c) * TOUT + t], qs[c], s);
        gate[tid] = sigm(s);
    }
    __syncthreads();

    float m = -INFINITY;
    const float* hr = &d_hmain[((size_t)b * C_ + tid) * TOUT + t0];
    for (int tt = 0; tt < nt; tt++)
        m = fmaxf(m, hr[tt] * gate[tt]);
    atomicMaxF(&out[b * C_ + tid], m);
}

extern "C" void kernel_launch(void* const* d_in, const int* in_sizes, int n_in,
                              void* d_out, int out_size) {
    const float* x   = (const float*)d_in[0];
    const float* ccw = (const float*)d_in[1];
    const float* ccb = (const float*)d_in[2];
    const float* csw = (const float*)d_in[3];
    const float* csb = (const float*)d_in[4];
    const float* mcw = (const float*)d_in[5];
    const float* mcb = (const float*)d_in[6];
    const float* msw = (const float*)d_in[7];
    const float* msb = (const float*)d_in[8];
    const float* pw  = (const float*)d_in[9];
    const float* pb  = (const float*)d_in[10];
    float* out = (float*)d_out;

    reorder_w<<<(NOUT * KDIM) / 256, 256>>>(ccw, mcw);
    init_red<<<2, 256>>>(out);

    dim3 g((TOUT + BM - 1) / BM, NOUT / BN, B_);   // (16, 4, 4)
    gemm_conv<<<g, 256>>>(x, ccb, mcb);

    epi_glu_share<<<dim3((TOUT + TT1 - 1) / TT1, B_), 256>>>(csw, csb, msw, msb);
    q_kernel<<<B_, C_>>>(pw, pb);
    epi_gate_max<<<dim3((TOUT + TT3 - 1) / TT3, B_), 128>>>(out);
}

// round 4
// speedup vs baseline: 2.2911x; 2.2911x over previous
#include <cuda_runtime.h>
#include <cuda_bf16.h>
#include <math.h>
#include <stdint.h>

// ---------------- problem constants ----------------
#define B_    4
#define E_    8
#define C_    128
#define NOUT  512          // ctx 0..255 (a|g), main 256..511 (a|g)
#define KW    512
#define T_    1000000
#define TOUT  1953
#define KDIM  4096
#define MROWS 7812         // B_ * TOUT flattened GEMM rows

// GEMM tiling
#define TMT  128           // CTA M tile
#define TNT  128           // CTA N tile
#define KC   32            // K chunk (bf16 elems)
#define NCH  (KDIM / KC)   // 128 chunks
#define MTILES 62          // ceil(7812/128)

// SMEM: 4 tiles (Ahi, Alo, Bhi, Blo), 128 rows x 32 bf16, padded row = 80 B
#define ROWB   80
#define TILEB  (128 * ROWB)          // 10240
#define OFF_AHI 0
#define OFF_ALO TILEB
#define OFF_BHI (2 * TILEB)
#define OFF_BLO (3 * TILEB)
#define STAGEB  (4 * TILEB)          // 40960
#define SMEM_DYN (2 * STAGEB)        // 81920

#define TT1 16
#define TT3 128

// ---------------- device scratch ----------------
__device__ __nv_bfloat16 d_whi[(size_t)NOUT * KDIM];    // 4 MB
__device__ __nv_bfloat16 d_wlo[(size_t)NOUT * KDIM];    // 4 MB
__device__ float d_y[(size_t)B_ * NOUT * TOUT];         // 16 MB
__device__ float d_hmain[(size_t)B_ * C_ * TOUT];       // 4 MB
__device__ float d_gct[B_ * C_];
__device__ float d_q[B_ * C_];

__device__ __forceinline__ float sigm(float v) { return 1.0f / (1.0f + expf(-v)); }
__device__ __forceinline__ float leaky(float v) { return v >= 0.0f ? v : 0.01f * v; }

__device__ __forceinline__ void atomicMaxF(float* addr, float val) {
    int* ia = (int*)addr;
    int old = __float_as_int(*addr);
    while (__int_as_float(old) < val) {
        int assumed = old;
        old = atomicCAS(ia, assumed, __float_as_int(val));
        if (old == assumed) break;
    }
}

__device__ __forceinline__ uint32_t smem_u32(const void* p) {
    uint32_t a;
    asm("{ .reg .u64 t; cvta.to.shared.u64 t, %1; cvt.u32.u64 %0, t; }" : "=r"(a) : "l"(p));
    return a;
}

__device__ __forceinline__ uint32_t packbf(__nv_bfloat16 a, __nv_bfloat16 b) {
    return (uint32_t)__bfloat16_as_ushort(a) | ((uint32_t)__bfloat16_as_ushort(b) << 16);
}

__device__ __forceinline__ void ldsm4(uint32_t* r, uint32_t addr) {
    asm volatile("ldmatrix.sync.aligned.m8n8.x4.shared.b16 {%0,%1,%2,%3}, [%4];"
        : "=r"(r[0]), "=r"(r[1]), "=r"(r[2]), "=r"(r[3]) : "r"(addr));
}

__device__ __forceinline__ void mma16816(float* d, const uint32_t* a, const uint32_t* b) {
    asm volatile("mma.sync.aligned.m16n8k16.row.col.f32.bf16.bf16.f32 "
        "{%0,%1,%2,%3}, {%4,%5,%6,%7}, {%8,%9}, {%0,%1,%2,%3};"
        : "+f"(d[0]), "+f"(d[1]), "+f"(d[2]), "+f"(d[3])
        : "r"(a[0]), "r"(a[1]), "r"(a[2]), "r"(a[3]), "r"(b[0]), "r"(b[1]));
}

// ---------------- 1) weight split: fp32 -> bf16 hi/lo, reordered ----------------
__global__ void conv_w(const float* __restrict__ cw, const float* __restrict__ mw) {
    int idx = blockIdx.x * blockDim.x + threadIdx.x;  // < NOUT*KDIM
    int o = idx >> 12;
    int k = idx & 4095;
    int e = k & 7;
    int kk = k >> 3;
    float v = (o < 256) ? cw[o * KDIM + e * KW + kk]
                        : mw[(o - 256) * KDIM + e * KW + kk];
    __nv_bfloat16 h = __float2bfloat16(v);
    d_whi[idx] = h;
    d_wlo[idx] = __float2bfloat16(v - __bfloat162float(h));
}

// ---------------- 2) init reductions ----------------
__global__ void init_red(float* __restrict__ out) {
    int i = blockIdx.x * blockDim.x + threadIdx.x;
    if (i < B_ * C_) {
        d_gct[i] = -INFINITY;
        out[i]   = -INFINITY;
    }
}

// ---------------- 3) bf16-split mma.sync GEMM: y = Xwin @ W^T ----------------
__global__ __launch_bounds__(256, 1)
void gemm_tc(const float* __restrict__ x,
             const float* __restrict__ ctx_b, const float* __restrict__ main_b) {
    extern __shared__ char smem[];
    const uint32_t sb = smem_u32(smem);

    const int tid  = threadIdx.x;
    const int wid  = tid >> 5;
    const int lane = tid & 31;
    const int nbase = blockIdx.x * TNT;     // 0..3 -> channel tile
    const int m0    = blockIdx.y * TMT;     // row tile
    const int wm = (wid >> 2) * 64;         // warp M offset in CTA tile
    const int wn = (wid & 3) * 32;          // warp N offset

    float acc[4][4][4];
#pragma unroll
    for (int i = 0; i < 4; i++)
#pragma unroll
        for (int j = 0; j < 4; j++)
#pragma unroll
            for (int k = 0; k < 4; k++) acc[i][j][k] = 0.0f;

    // per-thread A-load geometry: 4 float4 per chunk
    const float* aptr[4];
    int asmoff[4];
#pragma unroll
    for (int t = 0; t < 4; t++) {
        int idx = tid + t * 256;            // 0..1023
        int row = idx >> 3;                 // 0..127
        int c4  = idx & 7;                  // float4 within 32-float row
        int gr = m0 + row;
        if (gr < MROWS) {
            int bb = gr / TOUT;
            int tt = gr - bb * TOUT;
            aptr[t] = x + (size_t)bb * ((size_t)T_ * E_) + (size_t)tt * KDIM + c4 * 4;
        } else aptr[t] = nullptr;
        asmoff[t] = row * ROWB + c4 * 8;
    }
    // per-thread B-load geometry: 2 uint4 per chunk per version
    const __nv_bfloat16* bhsrc[2];
    const __nv_bfloat16* blsrc[2];
    int bsmoff[2];
#pragma unroll
    for (int t = 0; t < 2; t++) {
        int idx = tid + t * 256;            // 0..511
        int row = idx >> 2;                 // 0..127
        int c16 = idx & 3;
        int o = nbase + row;
        bhsrc[t] = d_whi + (size_t)o * KDIM + c16 * 8;
        blsrc[t] = d_wlo + (size_t)o * KDIM + c16 * 8;
        bsmoff[t] = row * ROWB + c16 * 16;
    }

    float4 pa[4];
    uint4 pbh[2], pbl[2];

    auto fetch = [&](int ch) {
        const int k0 = ch * KC;
#pragma unroll
        for (int t = 0; t < 4; t++)
            pa[t] = aptr[t] ? *reinterpret_cast<const float4*>(aptr[t] + k0)
                            : make_float4(0.f, 0.f, 0.f, 0.f);
#pragma unroll
        for (int t = 0; t < 2; t++) {
            pbh[t] = *reinterpret_cast<const uint4*>(bhsrc[t] + k0);
            pbl[t] = *reinterpret_cast<const uint4*>(blsrc[t] + k0);
        }
    };
    auto store = [&](int buf) {
        const uint32_t st = sb + buf * STAGEB;
#pragma unroll
        for (int t = 0; t < 4; t++) {
            float vx = pa[t].x, vy = pa[t].y, vz = pa[t].z, vw = pa[t].w;
            __nv_bfloat16 hx = __float2bfloat16(vx), hy = __float2bfloat16(vy);
            __nv_bfloat16 hz = __float2bfloat16(vz), hw = __float2bfloat16(vw);
            uint2 hi = make_uint2(packbf(hx, hy), packbf(hz, hw));
            uint2 lo = make_uint2(
                packbf(__float2bfloat16(vx - __bfloat162float(hx)),
                       __float2bfloat16(vy - __bfloat162float(hy))),
                packbf(__float2bfloat16(vz - __bfloat162float(hz)),
                       __float2bfloat16(vw - __bfloat162float(hw))));
            uint32_t ah = st + OFF_AHI + asmoff[t];
            uint32_t al = st + OFF_ALO + asmoff[t];
            asm volatile("st.shared.v2.b32 [%0], {%1,%2};" :: "r"(ah), "r"(hi.x), "r"(hi.y) : "memory");
            asm volatile("st.shared.v2.b32 [%0], {%1,%2};" :: "r"(al), "r"(lo.x), "r"(lo.y) : "memory");
        }
#pragma unroll
        for (int t = 0; t < 2; t++) {
            uint32_t bh = st + OFF_BHI + bsmoff[t];
            uint32_t bl = st + OFF_BLO + bsmoff[t];
            asm volatile("st.shared.v4.b32 [%0], {%1,%2,%3,%4};"
                :: "r"(bh), "r"(pbh[t].x), "r"(pbh[t].y), "r"(pbh[t].z), "r"(pbh[t].w) : "memory");
            asm volatile("st.shared.v4.b32 [%0], {%1,%2,%3,%4};"
                :: "r"(bl), "r"(pbl[t].x), "r"(pbl[t].y), "r"(pbl[t].z), "r"(pbl[t].w) : "memory");
        }
    };

    // ldmatrix lane geometry
    const int a_row = wm + (lane & 15);
    const int a_sel = lane >> 4;                         // k-seg half
    const int b_row = wn + ((lane >> 4) << 3) + (lane & 7);
    const int b_sel = (lane >> 3) & 1;

    fetch(0);
    store(0);
    __syncthreads();

    for (int ch = 0; ch < NCH; ch++) {
        const int buf = ch & 1;
        if (ch + 1 < NCH) fetch(ch + 1);

        const uint32_t st = sb + buf * STAGEB;
#pragma unroll
        for (int s = 0; s < 2; s++) {
            uint32_t ah[4][4], al[4][4];
            const int aseg = (s * 2 + a_sel) * 16;
#pragma unroll
            for (int mt = 0; mt < 4; mt++) {
                uint32_t ar = st + (a_row + mt * 16) * ROWB + aseg;
                ldsm4(ah[mt], ar + OFF_AHI);
                ldsm4(al[mt], ar + OFF_ALO);
            }
            uint32_t bh[8], bl[8];
            const int bseg = (s * 2 + b_sel) * 16;
            {
                uint32_t br0 = st + b_row * ROWB + bseg;
                uint32_t br1 = st + (b_row + 16) * ROWB + bseg;
                ldsm4(bh + 0, br0 + OFF_BHI);
                ldsm4(bh + 4, br1 + OFF_BHI);
                ldsm4(bl + 0, br0 + OFF_BLO);
                ldsm4(bl + 4, br1 + OFF_BLO);
            }
#pragma unroll
            for (int mt = 0; mt < 4; mt++)
#pragma unroll
                for (int nt = 0; nt < 4; nt++) {
                    mma16816(acc[mt][nt], ah[mt], bh + nt * 2);
                    mma16816(acc[mt][nt], ah[mt], bl + nt * 2);
                    mma16816(acc[mt][nt], al[mt], bh + nt * 2);
                }
        }

        if (ch + 1 < NCH) store(buf ^ 1);
        __syncthreads();
    }

    // epilogue: add conv bias, write y[b][o][t]
#pragma unroll
    for (int mt = 0; mt < 4; mt++) {
#pragma unroll
        for (int nt = 0; nt < 4; nt++) {
            int m_lo = m0 + wm + mt * 16 + (lane >> 2);
            int o    = nbase + wn + nt * 8 + (lane & 3) * 2;
            float bias0 = (o < 256) ? __ldg(&ctx_b[o]) : __ldg(&main_b[o - 256]);
            float bias1 = (o + 1 < 256) ? __ldg(&ctx_b[o + 1]) : __ldg(&main_b[o + 1 - 256]);
#pragma unroll
            for (int half = 0; half < 2; half++) {
                int m = m_lo + half * 8;
                if (m >= MROWS) continue;
                int bb = m / TOUT;
                int tt = m - bb * TOUT;
                size_t base = ((size_t)bb * NOUT + o) * TOUT + tt;
                d_y[base]        = acc[mt][nt][half * 2 + 0] + bias0;
                d_y[base + TOUT] = acc[mt][nt][half * 2 + 1] + bias1;
            }
        }
    }
}

// ---------------- 4) GLU + 1x1 share conv + leaky; ctx->gct max, main->h ----------------
__global__ __launch_bounds__(256)
void epi_glu_share(const float* __restrict__ ws_ctx, const float* __restrict__ bs_ctx,
                   const float* __restrict__ ws_main, const float* __restrict__ bs_main) {
    const int b  = blockIdx.y;
    const int t0 = blockIdx.x * TT1;
    const int nt = min(TT1, TOUT - t0);
    const int tid = threadIdx.x;

    __shared__ float ytile[NOUT][TT1];

    for (int idx = tid; idx < NOUT * TT1; idx += 256) {
        int o = idx / TT1, tt = idx % TT1;
        ytile[o][tt] = (tt < nt) ? d_y[((size_t)b * NOUT + o) * TOUT + t0 + tt] : 0.0f;
    }
    __syncthreads();

    for (int idx = tid; idx < C_ * TT1; idx += 256) {
        int c = idx / TT1, tt = idx % TT1;
        float a1 = ytile[c][tt],          g1 = ytile[C_ + c][tt];
        float a2 = ytile[2 * C_ + c][tt], g2 = ytile[3 * C_ + c][tt];
        ytile[c][tt]          = a1 * sigm(g1);
        ytile[2 * C_ + c][tt] = a2 * sigm(g2);
    }
    __syncthreads();

    const int branch = tid >> 7;
    const int cp = tid & 127;
    const float* ws = branch ? ws_main : ws_ctx;
    const float* bs = branch ? bs_main : bs_ctx;
    const int rowbase = branch ? (2 * C_) : 0;

    float acc[TT1];
#pragma unroll
    for (int tt = 0; tt < TT1; tt++) acc[tt] = 0.0f;

    for (int c = 0; c < C_; c++) {
        float w = ws[cp * C_ + c];
        const float4* row = (const float4*)&ytile[rowbase + c][0];
        float4 v0 = row[0], v1 = row[1], v2 = row[2], v3 = row[3];
        acc[0]  = fmaf(w, v0.x, acc[0]);  acc[1]  = fmaf(w, v0.y, acc[1]);
        acc[2]  = fmaf(w, v0.z, acc[2]);  acc[3]  = fmaf(w, v0.w, acc[3]);
        acc[4]  = fmaf(w, v1.x, acc[4]);  acc[5]  = fmaf(w, v1.y, acc[5]);
        acc[6]  = fmaf(w, v1.z, acc[6]);  acc[7]  = fmaf(w, v1.w, acc[7]);
        acc[8]  = fmaf(w, v2.x, acc[8]);  acc[9]  = fmaf(w, v2.y, acc[9]);
        acc[10] = fmaf(w, v2.z, acc[10]); acc[11] = fmaf(w, v2.w, acc[11]);
        acc[12] = fmaf(w, v3.x, acc[12]); acc[13] = fmaf(w, v3.y, acc[13]);
        acc[14] = fmaf(w, v3.z, acc[14]); acc[15] = fmaf(w, v3.w, acc[15]);
    }
    float bias = bs[cp];
    if (branch == 0) {
        float m = -INFINITY;
        for (int tt = 0; tt < nt; tt++)
            m = fmaxf(m, leaky(acc[tt] + bias));
        atomicMaxF(&d_gct[b * C_ + cp], m);
    } else {
        for (int tt = 0; tt < nt; tt++)
            d_hmain[((size_t)b * C_ + cp) * TOUT + t0 + tt] = leaky(acc[tt] + bias);
    }
}

// ---------------- 5) q = tanh(gct @ Wp^T + bp) ----------------
__global__ void q_kernel(const float* __restrict__ wp, const float* __restrict__ bp) {
    int b = blockIdx.x;
    int c = threadIdx.x;
    __shared__ float g[C_];
    g[c] = d_gct[b * C_ + c];
    __syncthreads();
    float s = bp[c];
    for (int cp = 0; cp < C_; cp++)
        s = fmaf(g[cp], wp[c * C_ + cp], s);
    d_q[b * C_ + c] = tanhf(s);
}

// ---------------- 6) gate = sigmoid(h . q); out = max_t h*gate ----------------
__global__ void epi_gate_max(float* __restrict__ out) {
    const int b  = blockIdx.y;
    const int t0 = blockIdx.x * TT3;
    const int nt = min(TT3, TOUT - t0);
    const int tid = threadIdx.x;

    __shared__ float qs[C_];
    __shared__ float gate[TT3];
    qs[tid] = d_q[b * C_ + tid];
    __syncthreads();

    if (tid < nt) {
        int t = t0 + tid;
        float s = 0.0f;
        for (int c = 0; c < C_; c++)
            s = fmaf(d_hmain[((size_t)b * C_ + c) * TOUT + t], qs[c], s);
        gate[tid] = sigm(s);
    }
    __syncthreads();

    float m = -INFINITY;
    const float* hr = &d_hmain[((size_t)b * C_ + tid) * TOUT + t0];
    for (int tt = 0; tt < nt; tt++)
        m = fmaxf(m, hr[tt] * gate[tt]);
    atomicMaxF(&out[b * C_ + tid], m);
}

extern "C" void kernel_launch(void* const* d_in, const int* in_sizes, int n_in,
                              void* d_out, int out_size) {
    const float* x   = (const float*)d_in[0];
    const float* ccw = (const float*)d_in[1];
    const float* ccb = (const float*)d_in[2];
    const float* csw = (const float*)d_in[3];
    const float* csb = (const float*)d_in[4];
    const float* mcw = (const float*)d_in[5];
    const float* mcb = (const float*)d_in[6];
    const float* msw = (const float*)d_in[7];
    const float* msb = (const float*)d_in[8];
    const float* pw  = (const float*)d_in[9];
    const float* pb  = (const float*)d_in[10];
    float* out = (float*)d_out;

    cudaFuncSetAttribute(gemm_tc, cudaFuncAttributeMaxDynamicSharedMemorySize, SMEM_DYN);

    conv_w<<<(NOUT * KDIM) / 256, 256>>>(ccw, mcw);
    init_red<<<2, 256>>>(out);

    gemm_tc<<<dim3(4, MTILES), 256, SMEM_DYN>>>(x, ccb, mcb);

    epi_glu_share<<<dim3((TOUT + TT1 - 1) / TT1, B_), 256>>>(csw, csb, msw, msb);
    q_kernel<<<B_, C_>>>(pw, pb);
    epi_gate_max<<<dim3((TOUT + TT3 - 1) / TT3, B_), 128>>>(out);
}

// round 6
// speedup vs baseline: 2.7938x; 1.2194x over previous
#include <cuda_runtime.h>
#include <cuda_bf16.h>
#include <math.h>
#include <stdint.h>

// ---------------- problem constants ----------------
#define B_    4
#define E_    8
#define C_    128
#define NOUT  512          // ctx 0..255 (a|g), main 256..511 (a|g)
#define KW    512
#define T_    1000000
#define TOUT  1953
#define TPAD  2048         // padded time stride for d_y / d_hmain
#define KDIM  4096
#define MROWS 7812         // B_ * TOUT flattened GEMM rows

// conv GEMM tiling
#define TMT  128
#define TNT  128
#define KC   32
#define NCH  (KDIM / KC)   // 128
#define MTILES 62

// conv GEMM smem: 4 tiles (Ahi, Alo, Bhi, Blo), 128 rows x 32 bf16, row = 80 B
#define ROWB   80
#define TILEB  (128 * ROWB)
#define OFF_AHI 0
#define OFF_ALO TILEB
#define OFF_BHI (2 * TILEB)
#define OFF_BLO (3 * TILEB)
#define STAGEB  (4 * TILEB)          // 40960
#define SMEM_DYN (2 * STAGEB)        // 81920

// epi2 (share GEMM) smem: 4 tiles of 128 rows x 128 bf16, row = 272 B
#define SROWB   272
#define STILE   (128 * SROWB)        // 34816
#define S_WSHI  0
#define S_WSLO  STILE
#define S_GLHI  (2 * STILE)
#define S_GLLO  (3 * STILE)
#define SMEM_EPI (4 * STILE)         // 139264

#define TT3 128

// ---------------- device scratch ----------------
__device__ __nv_bfloat16 d_whi[(size_t)NOUT * KDIM];    // 4 MB
__device__ __nv_bfloat16 d_wlo[(size_t)NOUT * KDIM];    // 4 MB
__device__ __nv_bfloat16 d_shi[2 * C_ * C_];            // share weights hi
__device__ __nv_bfloat16 d_slo[2 * C_ * C_];            // share weights lo
__device__ float d_y[(size_t)B_ * NOUT * TPAD];         // ~16.8 MB (pad zero)
__device__ float d_hmain[(size_t)B_ * C_ * TPAD];       // ~4.2 MB
__device__ float d_gct[B_ * C_];
__device__ float d_q[B_ * C_];

__device__ __forceinline__ float sigm(float v) { return 1.0f / (1.0f + expf(-v)); }
__device__ __forceinline__ float leaky(float v) { return v >= 0.0f ? v : 0.01f * v; }

__device__ __forceinline__ void atomicMaxF(float* addr, float val) {
    int* ia = (int*)addr;
    int old = __float_as_int(*addr);
    while (__int_as_float(old) < val) {
        int assumed = old;
        old = atomicCAS(ia, assumed, __float_as_int(val));
        if (old == assumed) break;
    }
}

__device__ __forceinline__ uint32_t smem_u32(const void* p) {
    uint32_t a;
    asm("{ .reg .u64 t; cvta.to.shared.u64 t, %1; cvt.u32.u64 %0, t; }" : "=r"(a) : "l"(p));
    return a;
}
__device__ __forceinline__ uint32_t packbf(__nv_bfloat16 a, __nv_bfloat16 b) {
    return (uint32_t)__bfloat16_as_ushort(a) | ((uint32_t)__bfloat16_as_ushort(b) << 16);
}
__device__ __forceinline__ void ldsm4(uint32_t* r, uint32_t addr) {
    asm volatile("ldmatrix.sync.aligned.m8n8.x4.shared.b16 {%0,%1,%2,%3}, [%4];"
        : "=r"(r[0]), "=r"(r[1]), "=r"(r[2]), "=r"(r[3]) : "r"(addr));
}
__device__ __forceinline__ void ldsm4t(uint32_t* r, uint32_t addr) {
    asm volatile("ldmatrix.sync.aligned.m8n8.x4.trans.shared.b16 {%0,%1,%2,%3}, [%4];"
        : "=r"(r[0]), "=r"(r[1]), "=r"(r[2]), "=r"(r[3]) : "r"(addr));
}
__device__ __forceinline__ void mma16816(float* d, const uint32_t* a, const uint32_t* b) {
    asm volatile("mma.sync.aligned.m16n8k16.row.col.f32.bf16.bf16.f32 "
        "{%0,%1,%2,%3}, {%4,%5,%6,%7}, {%8,%9}, {%0,%1,%2,%3};"
        : "+f"(d[0]), "+f"(d[1]), "+f"(d[2]), "+f"(d[3])
        : "r"(a[0]), "r"(a[1]), "r"(a[2]), "r"(a[3]), "r"(b[0]), "r"(b[1]));
}
#define CP_ASYNC16(dst, src) \
    asm volatile("cp.async.ca.shared.global [%0], [%1], 16;" :: "r"(dst), "l"(src) : "memory")
#define CP_COMMIT() asm volatile("cp.async.commit_group;" ::: "memory")
#define CP_WAIT0()  asm volatile("cp.async.wait_group 0;" ::: "memory")

// ---------------- 1) weight splits ----------------
__global__ void conv_w(const float* __restrict__ cw, const float* __restrict__ mw) {
    int idx = blockIdx.x * blockDim.x + threadIdx.x;  // < NOUT*KDIM
    int o = idx >> 12;
    int k = idx & 4095;
    int e = k & 7;
    int kk = k >> 3;
    float v = (o < 256) ? cw[o * KDIM + e * KW + kk]
                        : mw[(o - 256) * KDIM + e * KW + kk];
    __nv_bfloat16 h = __float2bfloat16(v);
    d_whi[idx] = h;
    d_wlo[idx] = __float2bfloat16(v - __bfloat162float(h));
}

__global__ void conv_s(const float* __restrict__ csw, const float* __restrict__ msw) {
    int idx = blockIdx.x * blockDim.x + threadIdx.x;  // < 2*128*128
    int branch = idx >> 14;
    int r = idx & 16383;
    float v = branch ? msw[r] : csw[r];
    __nv_bfloat16 h = __float2bfloat16(v);
    d_shi[idx] = h;
    d_slo[idx] = __float2bfloat16(v - __bfloat162float(h));
}

// ---------------- 2) init reductions ----------------
__global__ void init_red(float* __restrict__ out) {
    int i = blockIdx.x * blockDim.x + threadIdx.x;
    if (i < B_ * C_) {
        d_gct[i] = -INFINITY;
        out[i]   = -INFINITY;
    }
}

// ---------------- 3) bf16-split mma.sync conv GEMM: y = Xwin @ W^T ----------------
__global__ __launch_bounds__(256, 2)
void gemm_tc(const float* __restrict__ x,
             const float* __restrict__ ctx_b, const float* __restrict__ main_b) {
    extern __shared__ char smem[];
    const uint32_t sb = smem_u32(smem);

    const int tid  = threadIdx.x;
    const int wid  = tid >> 5;
    const int lane = tid & 31;
    const int nbase = blockIdx.x * TNT;
    const int m0    = blockIdx.y * TMT;
    const int wm = (wid >> 2) * 64;
    const int wn = (wid & 3) * 32;

    float acc[4][4][4];
#pragma unroll
    for (int i = 0; i < 4; i++)
#pragma unroll
        for (int j = 0; j < 4; j++)
#pragma unroll
            for (int k = 0; k < 4; k++) acc[i][j][k] = 0.0f;

    // A-load geometry (4 float4 per chunk per thread)
    const float* aptr[4];
    int asmoff[4];
#pragma unroll
    for (int t = 0; t < 4; t++) {
        int idx = tid + t * 256;
        int row = idx >> 3;
        int c4  = idx & 7;
        int gr = m0 + row;
        if (gr < MROWS) {
            int bb = gr / TOUT;
            int tt = gr - bb * TOUT;
            aptr[t] = x + (size_t)bb * ((size_t)T_ * E_) + (size_t)tt * KDIM + c4 * 4;
        } else aptr[t] = nullptr;
        asmoff[t] = row * ROWB + c4 * 8;
    }

    // B cp.async geometry: 2 chunks of 16B per version per thread
    auto cpasyncB = [&](int ch, int buf) {
        const int k0 = ch * KC;
        const uint32_t st = sb + buf * STAGEB;
#pragma unroll
        for (int t = 0; t < 2; t++) {
            int idx = tid + t * 256;       // 0..511
            int row = idx >> 2;            // 0..127
            int c16 = idx & 3;
            int o = nbase + row;
            int soff = row * ROWB + c16 * 16;
            CP_ASYNC16(st + OFF_BHI + soff, d_whi + (size_t)o * KDIM + k0 + c16 * 8);
            CP_ASYNC16(st + OFF_BLO + soff, d_wlo + (size_t)o * KDIM + k0 + c16 * 8);
        }
    };

    auto fetchStoreA = [&](int ch, int buf) {
        const int k0 = ch * KC;
        const uint32_t st = sb + buf * STAGEB;
#pragma unroll
        for (int t = 0; t < 4; t++) {
            float4 v = aptr[t] ? *reinterpret_cast<const float4*>(aptr[t] + k0)
                               : make_float4(0.f, 0.f, 0.f, 0.f);
            __nv_bfloat16 hx = __float2bfloat16(v.x), hy = __float2bfloat16(v.y);
            __nv_bfloat16 hz = __float2bfloat16(v.z), hw = __float2bfloat16(v.w);
            uint32_t h0 = packbf(hx, hy), h1 = packbf(hz, hw);
            uint32_t l0 = packbf(__float2bfloat16(v.x - __bfloat162float(hx)),
                                 __float2bfloat16(v.y - __bfloat162float(hy)));
            uint32_t l1 = packbf(__float2bfloat16(v.z - __bfloat162float(hz)),
                                 __float2bfloat16(v.w - __bfloat162float(hw)));
            uint32_t ah = st + OFF_AHI + asmoff[t];
            uint32_t al = st + OFF_ALO + asmoff[t];
            asm volatile("st.shared.v2.b32 [%0], {%1,%2};" :: "r"(ah), "r"(h0), "r"(h1) : "memory");
            asm volatile("st.shared.v2.b32 [%0], {%1,%2};" :: "r"(al), "r"(l0), "r"(l1) : "memory");
        }
    };

    // ldmatrix lane geometry
    const int a_row = wm + (lane & 15);
    const int a_sel = lane >> 4;
    const int b_row = wn + ((lane >> 4) << 3) + (lane & 7);
    const int b_sel = (lane >> 3) & 1;

    // prologue: stage chunk 0 into buf 0
    cpasyncB(0, 0);
    CP_COMMIT();
    fetchStoreA(0, 0);
    CP_WAIT0();
    __syncthreads();

    for (int ch = 0; ch < NCH; ch++) {
        const int buf = ch & 1;
        if (ch + 1 < NCH) { cpasyncB(ch + 1, buf ^ 1); CP_COMMIT(); }

        const uint32_t st = sb + buf * STAGEB;
#pragma unroll
        for (int s = 0; s < 2; s++) {
            uint32_t ah[4][4], al[4][4];
            const int aseg = (s * 2 + a_sel) * 16;
#pragma unroll
            for (int mt = 0; mt < 4; mt++) {
                uint32_t ar = st + (a_row + mt * 16) * ROWB + aseg;
                ldsm4(ah[mt], ar + OFF_AHI);
                ldsm4(al[mt], ar + OFF_ALO);
            }
            uint32_t bh[8], bl[8];
            const int bseg = (s * 2 + b_sel) * 16;
            {
                uint32_t br0 = st + b_row * ROWB + bseg;
                uint32_t br1 = st + (b_row + 16) * ROWB + bseg;
                ldsm4(bh + 0, br0 + OFF_BHI);
                ldsm4(bh + 4, br1 + OFF_BHI);
                ldsm4(bl + 0, br0 + OFF_BLO);
                ldsm4(bl + 4, br1 + OFF_BLO);
            }
#pragma unroll
            for (int mt = 0; mt < 4; mt++)
#pragma unroll
                for (int nt = 0; nt < 4; nt++) {
                    mma16816(acc[mt][nt], ah[mt], bh + nt * 2);
                    mma16816(acc[mt][nt], ah[mt], bl + nt * 2);
                    mma16816(acc[mt][nt], al[mt], bh + nt * 2);
                }
        }

        if (ch + 1 < NCH) fetchStoreA(ch + 1, buf ^ 1);
        CP_WAIT0();
        __syncthreads();
    }

    // epilogue: add conv bias, write y[b][o][t] (stride TPAD)
#pragma unroll
    for (int mt = 0; mt < 4; mt++) {
#pragma unroll
        for (int nt = 0; nt < 4; nt++) {
            int m_lo = m0 + wm + mt * 16 + (lane >> 2);
            int o    = nbase + wn + nt * 8 + (lane & 3) * 2;
            float bias0 = (o < 256) ? __ldg(&ctx_b[o]) : __ldg(&main_b[o - 256]);
            float bias1 = (o + 1 < 256) ? __ldg(&ctx_b[o + 1]) : __ldg(&main_b[o + 1 - 256]);
#pragma unroll
            for (int half = 0; half < 2; half++) {
                int m = m_lo + half * 8;
                if (m >= MROWS) continue;
                int bb = m / TOUT;
                int tt = m - bb * TOUT;
                size_t base = ((size_t)bb * NOUT + o) * TPAD + tt;
                d_y[base]        = acc[mt][nt][half * 2 + 0] + bias0;
                d_y[base + TPAD] = acc[mt][nt][half * 2 + 1] + bias1;
            }
        }
    }
}

// ---------------- 4) share GEMM: GLU -> mma -> leaky -> gct max / hmain ----------------
__global__ __launch_bounds__(256, 1)
void epi2(const float* __restrict__ bs_ctx, const float* __restrict__ bs_main) {
    extern __shared__ char smem[];
    const uint32_t sb = smem_u32(smem);

    const int tid  = threadIdx.x;
    const int wid  = tid >> 5;
    const int lane = tid & 31;
    const int tcb    = blockIdx.x;          // t tile (0..15)
    const int branch = blockIdx.y;          // 0 ctx, 1 main
    const int b      = blockIdx.z;
    const int t0 = tcb * 128;

    // stage share weights (branch) hi/lo via cp.async
    {
        const __nv_bfloat16* wh = d_shi + branch * (C_ * C_);
        const __nv_bfloat16* wl = d_slo + branch * (C_ * C_);
        for (int i = tid; i < 2048; i += 256) {
            int row = i >> 4, j = i & 15;
            uint32_t soff = row * SROWB + j * 16;
            CP_ASYNC16(sb + S_WSHI + soff, wh + row * C_ + j * 8);
            CP_ASYNC16(sb + S_WSLO + soff, wl + row * C_ + j * 8);
        }
        CP_COMMIT();
    }

    // compute GLU tile: glu[c][t] bf16 hi/lo, rows c (128) x 128 t
    {
        int c  = tid >> 1;
        int th = (tid & 1) * 64;
        const float* ya = d_y + ((size_t)(b * NOUT + branch * 256 + c)) * TPAD + t0 + th;
        const float* yg = ya + (size_t)C_ * TPAD;
        uint32_t dh = sb + S_GLHI + c * SROWB + th * 2;
        uint32_t dl = sb + S_GLLO + c * SROWB + th * 2;
#pragma unroll 4
        for (int i = 0; i < 64; i += 4) {
            float4 av = *reinterpret_cast<const float4*>(ya + i);
            float4 gv = *reinterpret_cast<const float4*>(yg + i);
            float v0 = av.x * sigm(gv.x);
            float v1 = av.y * sigm(gv.y);
            float v2 = av.z * sigm(gv.z);
            float v3 = av.w * sigm(gv.w);
            __nv_bfloat16 h0 = __float2bfloat16(v0), h1 = __float2bfloat16(v1);
            __nv_bfloat16 h2 = __float2bfloat16(v2), h3 = __float2bfloat16(v3);
            uint32_t ph0 = packbf(h0, h1), ph1 = packbf(h2, h3);
            uint32_t pl0 = packbf(__float2bfloat16(v0 - __bfloat162float(h0)),
                                  __float2bfloat16(v1 - __bfloat162float(h1)));
            uint32_t pl1 = packbf(__float2bfloat16(v2 - __bfloat162float(h2)),
                                  __float2bfloat16(v3 - __bfloat162float(h3)));
            asm volatile("st.shared.v2.b32 [%0], {%1,%2};" :: "r"(dh + i * 2), "r"(ph0), "r"(ph1) : "memory");
            asm volatile("st.shared.v2.b32 [%0], {%1,%2};" :: "r"(dl + i * 2), "r"(pl0), "r"(pl1) : "memory");
        }
    }
    CP_WAIT0();
    __syncthreads();

    // mma: D[cp][t] = Ws @ glu ; warp tile 64x32
    const int wm = (wid >> 2) * 64;
    const int wn = (wid & 3) * 32;
    float acc[4][4][4];
#pragma unroll
    for (int i = 0; i < 4; i++)
#pragma unroll
        for (int j = 0; j < 4; j++)
#pragma unroll
            for (int k = 0; k < 4; k++) acc[i][j][k] = 0.0f;

    const int a_row = wm + (lane & 15);
    const int a_sel = lane >> 4;
#pragma unroll
    for (int ks = 0; ks < 8; ks++) {
        uint32_t ah[4][4], al[4][4];
        const int aseg = (ks * 16 + a_sel * 8) * 2;
#pragma unroll
        for (int mt = 0; mt < 4; mt++) {
            uint32_t ar = sb + (a_row + mt * 16) * SROWB + aseg;
            ldsm4(ah[mt], ar + S_WSHI);
            ldsm4(al[mt], ar + S_WSLO);
        }
        uint32_t bh[8], bl[8];
        const uint32_t brow = (ks * 16 + (lane & 15)) * SROWB;
#pragma unroll
        for (int nt2 = 0; nt2 < 2; nt2++) {
            uint32_t baddr = sb + brow + (wn + nt2 * 16 + (lane >> 4) * 8) * 2;
            ldsm4t(bh + nt2 * 4, baddr + S_GLHI);
            ldsm4t(bl + nt2 * 4, baddr + S_GLLO);
        }
#pragma unroll
        for (int mt = 0; mt < 4; mt++)
#pragma unroll
            for (int nt = 0; nt < 4; nt++) {
                mma16816(acc[mt][nt], ah[mt], bh + nt * 2);
                mma16816(acc[mt][nt], ah[mt], bl + nt * 2);
                mma16816(acc[mt][nt], al[mt], bh + nt * 2);
            }
    }

    // fragment epilogue
    const float* bs = branch ? bs_main : bs_ctx;
#pragma unroll
    for (int mt = 0; mt < 4; mt++) {
        int r0 = wm + mt * 16 + (lane >> 2);
        int r1 = r0 + 8;
        float bias0 = __ldg(&bs[r0]);
        float bias1 = __ldg(&bs[r1]);
        if (branch == 0) {
            float m0v = -INFINITY, m1v = -INFINITY;
#pragma unroll
            for (int nt = 0; nt < 4; nt++) {
                int tb = t0 + wn + nt * 8 + (lane & 3) * 2;
#pragma unroll
                for (int j = 0; j < 2; j++) {
                    if (tb + j < TOUT) {
                        m0v = fmaxf(m0v, leaky(acc[mt][nt][j] + bias0));
                        m1v = fmaxf(m1v, leaky(acc[mt][nt][2 + j] + bias1));
                    }
                }
            }
            m0v = fmaxf(m0v, __shfl_xor_sync(0xffffffffu, m0v, 1));
            m0v = fmaxf(m0v, __shfl_xor_sync(0xffffffffu, m0v, 2));
            m1v = fmaxf(m1v, __shfl_xor_sync(0xffffffffu, m1v, 1));
            m1v = fmaxf(m1v, __shfl_xor_sync(0xffffffffu, m1v, 2));
            if ((lane & 3) == 0) {
                atomicMaxF(&d_gct[b * C_ + r0], m0v);
                atomicMaxF(&d_gct[b * C_ + r1], m1v);
            }
        } else {
            float* h0 = d_hmain + ((size_t)b * C_ + r0) * TPAD;
            float* h1 = d_hmain + ((size_t)b * C_ + r1) * TPAD;
#pragma unroll
            for (int nt = 0; nt < 4; nt++) {
                int tb = t0 + wn + nt * 8 + (lane & 3) * 2;
                float v00 = leaky(acc[mt][nt][0] + bias0);
                float v01 = leaky(acc[mt][nt][1] + bias0);
                float v10 = leaky(acc[mt][nt][2] + bias1);
                float v11 = leaky(acc[mt][nt][3] + bias1);
                if (tb + 1 < TOUT) {
                    *reinterpret_cast<float2*>(h0 + tb) = make_float2(v00, v01);
                    *reinterpret_cast<float2*>(h1 + tb) = make_float2(v10, v11);
                } else if (tb < TOUT) {
                    h0[tb] = v00;
                    h1[tb] = v10;
                }
            }
        }
    }
}

// ---------------- 5) q = tanh(gct @ Wp^T + bp) ----------------
__global__ void q_kernel(const float* __restrict__ wp, const float* __restrict__ bp) {
    int b = blockIdx.x;
    int c = threadIdx.x;
    __shared__ float g[C_];
    g[c] = d_gct[b * C_ + c];
    __syncthreads();
    float s = bp[c];
    for (int cp = 0; cp < C_; cp++)
        s = fmaf(g[cp], wp[c * C_ + cp], s);
    d_q[b * C_ + c] = tanhf(s);
}

// ---------------- 6) gate = sigmoid(h . q); out = max_t h*gate ----------------
__global__ void epi_gate_max(float* __restrict__ out) {
    const int b  = blockIdx.y;
    const int t0 = blockIdx.x * TT3;
    const int nt = min(TT3, TOUT - t0);
    const int tid = threadIdx.x;

    __shared__ float qs[C_];
    __shared__ float gate[TT3];
    qs[tid] = d_q[b * C_ + tid];
    __syncthreads();

    if (tid < nt) {
        int t = t0 + tid;
        float s = 0.0f;
        for (int c = 0; c < C_; c++)
            s = fmaf(d_hmain[((size_t)b * C_ + c) * TPAD + t], qs[c], s);
        gate[tid] = sigm(s);
    }
    __syncthreads();

    float m = -INFINITY;
    const float* hr = &d_hmain[((size_t)b * C_ + tid) * TPAD + t0];
    for (int tt = 0; tt < nt; tt++)
        m = fmaxf(m, hr[tt] * gate[tt]);
    atomicMaxF(&out[b * C_ + tid], m);
}

extern "C" void kernel_launch(void* const* d_in, const int* in_sizes, int n_in,
                              void* d_out, int out_size) {
    const float* x   = (const float*)d_in[0];
    const float* ccw = (const float*)d_in[1];
    const float* ccb = (const float*)d_in[2];
    const float* csw = (const float*)d_in[3];
    const float* csb = (const float*)d_in[4];
    const float* mcw = (const float*)d_in[5];
    const float* mcb = (const float*)d_in[6];
    const float* msw = (const float*)d_in[7];
    const float* msb = (const float*)d_in[8];
    const float* pw  = (const float*)d_in[9];
    const float* pb  = (const float*)d_in[10];
    float* out = (float*)d_out;

    cudaFuncSetAttribute(gemm_tc, cudaFuncAttributeMaxDynamicSharedMemorySize, SMEM_DYN);
    cudaFuncSetAttribute(epi2, cudaFuncAttributeMaxDynamicSharedMemorySize, SMEM_EPI);

    conv_w<<<(NOUT * KDIM) / 256, 256>>>(ccw, mcw);
    conv_s<<<(2 * C_ * C_) / 256, 256>>>(csw, msw);
    init_red<<<2, 256>>>(out);

    gemm_tc<<<dim3(4, MTILES), 256, SMEM_DYN>>>(x, ccb, mcb);

    epi2<<<dim3(16, 2, B_), 256, SMEM_EPI>>>(csb, msb);
    q_kernel<<<B_, C_>>>(pw, pb);
    epi_gate_max<<<dim3((TOUT + TT3 - 1) / TT3, B_), 128>>>(out);
}